// round 1
// baseline (speedup 1.0000x reference)
#include <cuda_runtime.h>

#define NA 1024
#define NC 6
#define HH 48
#define NB_BINS 36
#define K_SP 1728          // 36*48
#define CE 64
#define VFC 16
#define OUT_C 128          // 64 + 16 + 48
#define M_ROWS (NA * NC)   // 6144

// Scratch for pooled social features (allocation-free rule -> __device__ global)
__device__ float g_sp[M_ROWS * K_SP];

// ---------------------------------------------------------------------------
// Kernel A: social pooling. One block per (agent a, candidate c) row.
// ---------------------------------------------------------------------------
__global__ void __launch_bounds__(256) pool_kernel(
    const float* __restrict__ hidden,     // [NA, NC, 48]
    const float* __restrict__ position,   // [NA, NC, 2]
    const int*   __restrict__ ntt,        // [nb]
    int nb)
{
    const int row = blockIdx.x;           // a*NC + c
    const int a = row / NC;
    const int c = row % NC;
    const int tid = threadIdx.x;

    __shared__ float s_sum[NB_BINS * HH];
    __shared__ float s_cnt[NB_BINS];
    __shared__ int   s_bin[256];

    for (int j = tid; j < NB_BINS * HH; j += blockDim.x) s_sum[j] = 0.0f;
    if (tid < NB_BINS) s_cnt[tid] = 0.0f;

    // episode [start, end) containing agent a (redundant per-thread, cheap)
    int start = 0, end = 0, cum = 0;
    for (int i = 0; i < nb; i++) {
        int s = ntt[i];
        if (a >= cum && a < cum + s) { start = cum; end = cum + s; }
        cum += s;
    }

    const float px = position[(a * NC + c) * 2 + 0];
    const float py = position[(a * NC + c) * 2 + 1];
    const float rlogf = 0.34657359027997264f;   // log(RMAX/RMIN)/NUM_RINGS
    const float PIf   = 3.14159265358979323846f;

    __syncthreads();

    for (int b0 = start; b0 < end; b0 += blockDim.x) {
        int nbk = min((int)blockDim.x, end - b0);
        if (tid < nbk) {
            int b = b0 + tid;
            float qx = position[(b * NC + c) * 2 + 0];
            float qy = position[(b * NC + c) * 2 + 1];
            float xd = px - qx;
            float yd = py - qy;
            float dist = sqrtf(xd * xd + yd * yd);
            int ring = (int)floorf(logf(dist / 0.5f + 1e-6f) / rlogf);
            int bin = -1;
            if (ring >= 0 && ring < 6) {
                float theta = atan2f(yd, xd);
                int wedge = (int)floorf((theta + PIf - 1e-6f) / PIf / 2.0f * 6.0f);
                bin = ring * 6 + wedge;
                if (bin < 0 || bin >= NB_BINS) bin = -1;  // edge-case OOB guard
            }
            s_bin[tid] = bin;
            if (bin >= 0) atomicAdd(&s_cnt[bin], 1.0f);
        }
        __syncthreads();
        // accumulate hidden into bins: lanes take consecutive h -> conflict-free
        for (int idx = tid; idx < nbk * HH; idx += blockDim.x) {
            int b = idx / HH;
            int h = idx % HH;
            int bin = s_bin[b];
            if (bin >= 0)
                atomicAdd(&s_sum[bin * HH + h],
                          hidden[((b0 + b) * NC + c) * HH + h]);
        }
        __syncthreads();
    }

    // normalize (scatter-mean) and write the sp row
    for (int j = tid; j < K_SP; j += blockDim.x) {
        g_sp[row * K_SP + j] = s_sum[j] / fmaxf(s_cnt[j / HH], 1.0f);
    }
}

// ---------------------------------------------------------------------------
// Kernel B: fused GEMM [6144 x 1728] @ [1728 x 48] + bias + relu + concat.
// BM=48 -> exactly 128 blocks (one wave). Each thread: 3 rows x 3 cols.
// ---------------------------------------------------------------------------
#define BM 48
#define BK 16

__global__ void __launch_bounds__(256) gemm_fuse_kernel(
    const float* __restrict__ scene,      // [M_ROWS, 64]
    const float* __restrict__ velocity,   // [M_ROWS, 2]
    const float* __restrict__ Wv,         // [2, 16]
    const float* __restrict__ bv,         // [16]
    const float* __restrict__ Ws,         // [1728, 48]
    const float* __restrict__ bs,         // [48]
    float* __restrict__ out)              // [M_ROWS, 128]
{
    __shared__ float As[BM][BK + 1];      // +1 pad: kill bank conflicts
    __shared__ float Bs[BK][HH];

    const int m0 = blockIdx.x * BM;
    const int tid = threadIdx.x;
    const int tx = tid % 16;              // cols tx, tx+16, tx+32
    const int ty = tid / 16;              // rows ty*3 .. ty*3+2

    float acc[3][3] = {};

    for (int k0 = 0; k0 < K_SP; k0 += BK) {
        for (int l = tid; l < BM * BK; l += 256) {
            int i = l / BK, j = l % BK;
            As[i][j] = g_sp[(m0 + i) * K_SP + k0 + j];
        }
        for (int l = tid; l < BK * HH; l += 256) {
            int i = l / HH, j = l % HH;
            Bs[i][j] = Ws[(k0 + i) * HH + j];
        }
        __syncthreads();
#pragma unroll
        for (int kk = 0; kk < BK; kk++) {
            float rA[3], rB[3];
#pragma unroll
            for (int i = 0; i < 3; i++) rA[i] = As[ty * 3 + i][kk];
#pragma unroll
            for (int j = 0; j < 3; j++) rB[j] = Bs[kk][tx + 16 * j];
#pragma unroll
            for (int i = 0; i < 3; i++)
#pragma unroll
                for (int j = 0; j < 3; j++)
                    acc[i][j] += rA[i] * rB[j];
        }
        __syncthreads();
    }

    // sp_enc -> cols [80, 128)
#pragma unroll
    for (int i = 0; i < 3; i++) {
        int row = m0 + ty * 3 + i;
#pragma unroll
        for (int j = 0; j < 3; j++) {
            int col = tx + 16 * j;
            out[row * OUT_C + 80 + col] = fmaxf(acc[i][j] + bs[col], 0.0f);
        }
    }
    // scene passthrough -> cols [0, 64)
    for (int l = tid; l < BM * CE; l += 256) {
        int r = l / CE, cc = l % CE;
        out[(m0 + r) * OUT_C + cc] = scene[(m0 + r) * CE + cc];
    }
    // velocity encoder -> cols [64, 80)
    for (int l = tid; l < BM * VFC; l += 256) {
        int r = l / VFC, o = l % VFC;
        int row = m0 + r;
        float v = velocity[row * 2 + 0] * Wv[o]
                + velocity[row * 2 + 1] * Wv[VFC + o] + bv[o];
        out[row * OUT_C + 64 + o] = fmaxf(v, 0.0f);
    }
}

// ---------------------------------------------------------------------------
extern "C" void kernel_launch(void* const* d_in, const int* in_sizes, int n_in,
                              void* d_out, int out_size)
{
    const float* hidden   = (const float*)d_in[0];
    const float* velocity = (const float*)d_in[1];
    const float* position = (const float*)d_in[2];
    const float* scene    = (const float*)d_in[3];
    const int*   ntt      = (const int*)d_in[4];
    const float* Wv       = (const float*)d_in[5];
    const float* bv       = (const float*)d_in[6];
    const float* Ws       = (const float*)d_in[7];
    const float* bs       = (const float*)d_in[8];
    float* out = (float*)d_out;
    int nb = in_sizes[4];

    pool_kernel<<<M_ROWS, 256>>>(hidden, position, ntt, nb);
    gemm_fuse_kernel<<<M_ROWS / BM, 256>>>(scene, velocity, Wv, bv, Ws, bs, out);
}

// round 3
// speedup vs baseline: 2.7432x; 2.7432x over previous
#include <cuda_runtime.h>

#define NA 1024
#define NC 6
#define HH 48
#define NB_BINS 36
#define K_SP 1728          // 36*48
#define CE 64
#define VFC 16
#define OUT_C 128          // 64 + 16 + 48
#define M_ROWS (NA * NC)   // 6144

#define BM 64
#define BN 48
#define BK 32
#define SPLIT 6
#define K_PER_SPLIT (K_SP / SPLIT)   // 288

// Scratch (allocation-free rule -> __device__ globals)
__device__ float g_sp[M_ROWS * K_SP];            // pooled features [6144, 1728]
__device__ float g_part[SPLIT * M_ROWS * BN];    // split-K partials

// ---------------------------------------------------------------------------
// Kernel A: social pooling. One block per (agent a, candidate c) row.
// ---------------------------------------------------------------------------
__global__ void __launch_bounds__(256) pool_kernel(
    const float* __restrict__ hidden,     // [NA, NC, 48]
    const float* __restrict__ position,   // [NA, NC, 2]
    const int*   __restrict__ ntt,        // [nb]
    int nb)
{
    const int row = blockIdx.x;           // a*NC + c
    const int a = row / NC;
    const int c = row % NC;
    const int tid = threadIdx.x;

    __shared__ float s_sum[NB_BINS * HH];
    __shared__ float s_cnt[NB_BINS];
    __shared__ int   s_bin[256];

    for (int j = tid; j < NB_BINS * HH; j += blockDim.x) s_sum[j] = 0.0f;
    if (tid < NB_BINS) s_cnt[tid] = 0.0f;

    // episode [start, end) containing agent a
    int start = 0, end = 0, cum = 0;
    for (int i = 0; i < nb; i++) {
        int s = ntt[i];
        if (a >= cum && a < cum + s) { start = cum; end = cum + s; }
        cum += s;
    }

    const float px = position[(a * NC + c) * 2 + 0];
    const float py = position[(a * NC + c) * 2 + 1];
    const float rlogf = 0.34657359027997264f;   // log(RMAX/RMIN)/NUM_RINGS
    const float PIf   = 3.14159265358979323846f;

    __syncthreads();

    for (int b0 = start; b0 < end; b0 += blockDim.x) {
        int nbk = min((int)blockDim.x, end - b0);
        if (tid < nbk) {
            int b = b0 + tid;
            float qx = position[(b * NC + c) * 2 + 0];
            float qy = position[(b * NC + c) * 2 + 1];
            float xd = px - qx;
            float yd = py - qy;
            float dist = sqrtf(xd * xd + yd * yd);
            int ring = (int)floorf(logf(dist / 0.5f + 1e-6f) / rlogf);
            int bin = -1;
            if (ring >= 0 && ring < 6) {
                float theta = atan2f(yd, xd);
                int wedge = (int)floorf((theta + PIf - 1e-6f) / PIf / 2.0f * 6.0f);
                bin = ring * 6 + wedge;
                if (bin < 0 || bin >= NB_BINS) bin = -1;
            }
            s_bin[tid] = bin;
            if (bin >= 0) atomicAdd(&s_cnt[bin], 1.0f);
        }
        __syncthreads();
        for (int idx = tid; idx < nbk * HH; idx += blockDim.x) {
            int b = idx / HH;
            int h = idx % HH;
            int bin = s_bin[b];
            if (bin >= 0)
                atomicAdd(&s_sum[bin * HH + h],
                          hidden[((b0 + b) * NC + c) * HH + h]);
        }
        __syncthreads();
    }

    for (int j = tid; j < K_SP; j += blockDim.x) {
        g_sp[row * K_SP + j] = s_sum[j] / fmaxf(s_cnt[j / HH], 1.0f);
    }
}

// ---------------------------------------------------------------------------
// Kernel B: split-K GEMM [6144 x 1728] @ [1728 x 48] -> partials.
// grid (96, 6); block 192 threads; 4x4 register tile; float4 smem reads.
// ---------------------------------------------------------------------------
#define BSTRIDE 52   // padded Bs row stride (words), float4-aligned

__global__ void __launch_bounds__(192) gemm_split_kernel(
    const float* __restrict__ Ws)         // [1728, 48]
{
    __shared__ float As[BM][BK + 4];      // stride 36
    __shared__ float Bs[BK][BSTRIDE];     // stride 52

    const int m0 = blockIdx.x * BM;
    const int k_base = blockIdx.y * K_PER_SPLIT;
    const int tid = threadIdx.x;
    const int tx = tid % 12;              // cols tx*4 .. tx*4+3
    const int ty = tid / 12;              // rows ty*4 .. ty*4+3

    float acc[4][4] = {};

    for (int kt = 0; kt < K_PER_SPLIT; kt += BK) {
        const int k0 = k_base + kt;
        // As: 64 rows x 32 k = 512 float4
        for (int l = tid; l < (BM * BK) / 4; l += 192) {
            int i = l / (BK / 4);
            int j = (l % (BK / 4)) * 4;
            *(float4*)&As[i][j] = *(const float4*)&g_sp[(m0 + i) * K_SP + k0 + j];
        }
        // Bs: 32 k x 48 cols = 384 float4
        for (int l = tid; l < (BK * BN) / 4; l += 192) {
            int i = l / (BN / 4);
            int j = (l % (BN / 4)) * 4;
            *(float4*)&Bs[i][j] = *(const float4*)&Ws[(k0 + i) * BN + j];
        }
        __syncthreads();

#pragma unroll
        for (int kk = 0; kk < BK; kk += 4) {
            float a[4][4], b[4][4];
#pragma unroll
            for (int r = 0; r < 4; r++)
                *(float4*)a[r] = *(const float4*)&As[ty * 4 + r][kk];   // a[r][q] = A(row r, k kk+q)
#pragma unroll
            for (int q = 0; q < 4; q++)
                *(float4*)b[q] = *(const float4*)&Bs[kk + q][tx * 4];   // b[q][c] = B(k kk+q, col c)
#pragma unroll
            for (int q = 0; q < 4; q++)
#pragma unroll
                for (int r = 0; r < 4; r++)
#pragma unroll
                    for (int c = 0; c < 4; c++)
                        acc[r][c] += a[r][q] * b[q][c];
        }
        __syncthreads();
    }

    // write partials
#pragma unroll
    for (int r = 0; r < 4; r++) {
        float4 v = make_float4(acc[r][0], acc[r][1], acc[r][2], acc[r][3]);
        *(float4*)&g_part[((blockIdx.y * M_ROWS) + m0 + ty * 4 + r) * BN + tx * 4] = v;
    }
}

// ---------------------------------------------------------------------------
// Kernel C: epilogue — sum split-K partials + bias + relu, plus concat of
// scene passthrough and the tiny velocity encoder.
// ---------------------------------------------------------------------------
__global__ void __launch_bounds__(256) epilogue_kernel(
    const float* __restrict__ scene,      // [M_ROWS, 64]
    const float* __restrict__ velocity,   // [M_ROWS, 2]
    const float* __restrict__ Wv,         // [2, 16]
    const float* __restrict__ bv,         // [16]
    const float* __restrict__ bs,         // [48]
    float* __restrict__ out)              // [M_ROWS, 128]
{
    int idx = blockIdx.x * blockDim.x + threadIdx.x;
    if (idx >= M_ROWS * OUT_C) return;
    int row = idx / OUT_C;
    int col = idx % OUT_C;
    float v;
    if (col < CE) {
        v = scene[row * CE + col];
    } else if (col < CE + VFC) {
        int o = col - CE;
        v = fmaxf(velocity[row * 2 + 0] * Wv[o]
                + velocity[row * 2 + 1] * Wv[VFC + o] + bv[o], 0.0f);
    } else {
        int c = col - CE - VFC;
        float s = bs[c];
#pragma unroll
        for (int p = 0; p < SPLIT; p++)
            s += g_part[(p * M_ROWS + row) * BN + c];
        v = fmaxf(s, 0.0f);
    }
    out[idx] = v;
}

// ---------------------------------------------------------------------------
extern "C" void kernel_launch(void* const* d_in, const int* in_sizes, int n_in,
                              void* d_out, int out_size)
{
    const float* hidden   = (const float*)d_in[0];
    const float* velocity = (const float*)d_in[1];
    const float* position = (const float*)d_in[2];
    const float* scene    = (const float*)d_in[3];
    const int*   ntt      = (const int*)d_in[4];
    const float* Wv       = (const float*)d_in[5];
    const float* bv       = (const float*)d_in[6];
    const float* Ws       = (const float*)d_in[7];
    const float* bs       = (const float*)d_in[8];
    float* out = (float*)d_out;
    int nb = in_sizes[4];

    pool_kernel<<<M_ROWS, 256>>>(hidden, position, ntt, nb);
    gemm_split_kernel<<<dim3(M_ROWS / BM, SPLIT), 192>>>(Ws);
    epilogue_kernel<<<(M_ROWS * OUT_C + 255) / 256, 256>>>(
        scene, velocity, Wv, bv, bs, out);
}

// round 4
// speedup vs baseline: 3.7020x; 1.3495x over previous
#include <cuda_runtime.h>

#define NA 1024
#define NC 6
#define HH 48
#define NB_BINS 36
#define K_SP 1728          // 36*48
#define CE 64
#define VFC 16
#define OUT_C 128          // 64 + 16 + 48
#define M_ROWS (NA * NC)   // 6144
#define MAXE 512           // max supported episode size

// hW[row=(b*NC+c), bin*48+n] = hidden[row,:] @ Ws[bin*48:(bin+1)*48, :]
__device__ float g_hw[M_ROWS * K_SP];

// ---------------------------------------------------------------------------
// Kernel P: hW precompute. grid (M_ROWS/128, 36). block 256.
// A transposed in smem (conflict-free float4 reads). Full K=48, no k-loop.
// ---------------------------------------------------------------------------
#define PM 128
#define ASTRIDE (PM + 4)   // 132

__global__ void __launch_bounds__(256) hw_kernel(
    const float* __restrict__ hidden,     // [M_ROWS, 48]
    const float* __restrict__ Ws)         // [1728, 48]
{
    __shared__ float Asm[HH][ASTRIDE];    // A^T : Asm[k][m]
    __shared__ float Bsm[HH][HH];         // Bsm[k][n] = Ws[bin*48+k][n]

    const int m0  = blockIdx.x * PM;
    const int bin = blockIdx.y;
    const int tid = threadIdx.x;

    // load A transposed: 128 rows x 48 k  (1536 float4)
    for (int l = tid; l < (PM * HH) / 4; l += 256) {
        int m  = l / (HH / 4);
        int kq = (l % (HH / 4)) * 4;
        float4 v = *(const float4*)&hidden[(m0 + m) * HH + kq];
        Asm[kq + 0][m] = v.x;
        Asm[kq + 1][m] = v.y;
        Asm[kq + 2][m] = v.z;
        Asm[kq + 3][m] = v.w;
    }
    // load B block: Ws rows [bin*48, bin*48+48) -- contiguous 9 KB
    for (int l = tid; l < (HH * HH) / 4; l += 256) {
        int i = l / (HH / 4);
        int j = (l % (HH / 4)) * 4;
        *(float4*)&Bsm[i][j] = *(const float4*)&Ws[(bin * HH + i) * HH + j];
    }
    __syncthreads();

    const int ty = tid / 8;               // rows ty*4 .. ty*4+3   (32 groups)
    const int tx = tid % 8;               // cols tx*6 .. tx*6+5   (8 groups)

    float acc[4][6] = {};
#pragma unroll 8
    for (int k = 0; k < HH; k++) {
        float4 a = *(const float4*)&Asm[k][ty * 4];
        float2 b01 = *(const float2*)&Bsm[k][tx * 6 + 0];
        float2 b23 = *(const float2*)&Bsm[k][tx * 6 + 2];
        float2 b45 = *(const float2*)&Bsm[k][tx * 6 + 4];
        float av[4] = {a.x, a.y, a.z, a.w};
        float bv[6] = {b01.x, b01.y, b23.x, b23.y, b45.x, b45.y};
#pragma unroll
        for (int r = 0; r < 4; r++)
#pragma unroll
            for (int j = 0; j < 6; j++)
                acc[r][j] += av[r] * bv[j];
    }

#pragma unroll
    for (int r = 0; r < 4; r++) {
        int row = m0 + ty * 4 + r;
        float* dst = &g_hw[row * K_SP + bin * HH + tx * 6];
#pragma unroll
        for (int j = 0; j < 6; j++) dst[j] = acc[r][j];
    }
}

// ---------------------------------------------------------------------------
// Kernel Q: per (a,c) row — bin the episode's agents, gather-sum hW rows,
// bias+relu, plus fused scene passthrough and velocity encoder.
// grid M_ROWS, block 192 (= 4 b-groups x 48 n).
// ---------------------------------------------------------------------------
__global__ void __launch_bounds__(192) gather_kernel(
    const float* __restrict__ position,   // [M_ROWS, 2]
    const int*   __restrict__ ntt,        // [nb]
    const float* __restrict__ scene,      // [M_ROWS, 64]
    const float* __restrict__ velocity,   // [M_ROWS, 2]
    const float* __restrict__ Wv,         // [2, 16]
    const float* __restrict__ bv,         // [16]
    const float* __restrict__ bs,         // [48]
    float* __restrict__ out,              // [M_ROWS, 128]
    int nb)
{
    const int row = blockIdx.x;           // a*NC + c
    const int a = row / NC;
    const int c = row % NC;
    const int tid = threadIdx.x;

    __shared__ int   s_bin[MAXE];
    __shared__ int   s_cnt[NB_BINS];
    __shared__ float s_inv[NB_BINS];
    __shared__ float s_red[4][HH];

    if (tid < NB_BINS) s_cnt[tid] = 0;

    // episode [start, end) containing agent a
    int start = 0, end = 0, cum = 0;
    for (int i = 0; i < nb; i++) {
        int s = ntt[i];
        if (a >= cum && a < cum + s) { start = cum; end = cum + s; }
        cum += s;
    }
    int esz = end - start;
    if (esz > MAXE) esz = MAXE;

    const float px = position[row * 2 + 0];
    const float py = position[row * 2 + 1];
    const float rlogf = 0.34657359027997264f;   // log(RMAX/RMIN)/NUM_RINGS
    const float PIf   = 3.14159265358979323846f;

    __syncthreads();

    // pass 1: bins + counts
    for (int b = tid; b < esz; b += 192) {
        int brow = (start + b) * NC + c;
        float xd = px - position[brow * 2 + 0];
        float yd = py - position[brow * 2 + 1];
        float dist = sqrtf(xd * xd + yd * yd);
        int ring = (int)floorf(logf(dist / 0.5f + 1e-6f) / rlogf);
        int bin = -1;
        if (ring >= 0 && ring < 6) {
            float theta = atan2f(yd, xd);
            int wedge = (int)floorf((theta + PIf - 1e-6f) / PIf / 2.0f * 6.0f);
            bin = ring * 6 + wedge;
            if (bin < 0 || bin >= NB_BINS) bin = -1;
        }
        s_bin[b] = bin;
        if (bin >= 0) atomicAdd(&s_cnt[bin], 1);
    }
    __syncthreads();
    if (tid < NB_BINS) s_inv[tid] = 1.0f / (float)max(s_cnt[tid], 1);
    __syncthreads();

    // pass 2: gather-sum over episode agents
    const int bq = tid / HH;              // 0..3
    const int n  = tid % HH;
    float acc = 0.0f;
    if (bq < 4) {
        for (int b = bq; b < esz; b += 4) {
            int bin = s_bin[b];
            if (bin >= 0) {
                int brow = (start + b) * NC + c;
                acc += g_hw[brow * K_SP + bin * HH + n] * s_inv[bin];
            }
        }
        s_red[bq][n] = acc;
    }

    // fused concat while the reduction lands: scene cols [0,64)
    for (int l = tid; l < CE; l += 192)
        out[row * OUT_C + l] = scene[row * CE + l];
    // velocity encoder cols [64,80)
    if (tid >= HH && tid < HH + VFC) {
        int o = tid - HH;
        float v = velocity[row * 2 + 0] * Wv[o]
                + velocity[row * 2 + 1] * Wv[VFC + o] + bv[o];
        out[row * OUT_C + CE + o] = fmaxf(v, 0.0f);
    }
    __syncthreads();

    // final reduce + bias + relu -> cols [80,128)
    if (tid < HH) {
        float t = s_red[0][tid] + s_red[1][tid] + s_red[2][tid] + s_red[3][tid];
        out[row * OUT_C + CE + VFC + tid] = fmaxf(t + bs[tid], 0.0f);
    }
}

// ---------------------------------------------------------------------------
extern "C" void kernel_launch(void* const* d_in, const int* in_sizes, int n_in,
                              void* d_out, int out_size)
{
    const float* hidden   = (const float*)d_in[0];
    const float* velocity = (const float*)d_in[1];
    const float* position = (const float*)d_in[2];
    const float* scene    = (const float*)d_in[3];
    const int*   ntt      = (const int*)d_in[4];
    const float* Wv       = (const float*)d_in[5];
    const float* bv       = (const float*)d_in[6];
    const float* Ws       = (const float*)d_in[7];
    const float* bs       = (const float*)d_in[8];
    float* out = (float*)d_out;
    int nb = in_sizes[4];

    hw_kernel<<<dim3(M_ROWS / PM, NB_BINS), 256>>>(hidden, Ws);
    gather_kernel<<<M_ROWS, 192>>>(position, ntt, scene, velocity,
                                   Wv, bv, bs, out, nb);
}

// round 5
// speedup vs baseline: 4.4070x; 1.1905x over previous
#include <cuda_runtime.h>

#define NA 1024
#define NC 6
#define HH 48
#define NB_BINS 36
#define K_SP 1728          // 36*48
#define CE 64
#define VFC 16
#define OUT_C 128          // 64 + 16 + 48
#define M_ROWS (NA * NC)   // 6144
#define MAXE 512           // max supported episode size

typedef unsigned long long u64;

// ---- packed f32x2 helpers (Blackwell FFMA2 pipe) --------------------------
__device__ __forceinline__ u64 pack2(float lo, float hi) {
    u64 r; asm("mov.b64 %0, {%1,%2};" : "=l"(r) : "f"(lo), "f"(hi)); return r;
}
__device__ __forceinline__ u64 fma2(u64 a, u64 b, u64 c) {
    u64 d; asm("fma.rn.f32x2 %0, %1, %2, %3;" : "=l"(d) : "l"(a), "l"(b), "l"(c));
    return d;
}
__device__ __forceinline__ float2 unpack2(u64 v) {
    float2 f; asm("mov.b64 {%0,%1}, %2;" : "=f"(f.x), "=f"(f.y) : "l"(v)); return f;
}

// hW[row=(b*NC+c), bin*48+n] = hidden[row,:] @ Ws[bin*48:(bin+1)*48, :]
__device__ float g_hw[M_ROWS * K_SP];

// ---------------------------------------------------------------------------
// Kernel P: hW precompute. grid (M_ROWS/128, 36). block 256.
// 4x6 thread tile, f32x2 packed accumulators (12 FFMA2 / k-iter / thread).
// ---------------------------------------------------------------------------
#define PM 128
#define ASTRIDE (PM + 4)   // 132

__global__ void __launch_bounds__(256) hw_kernel(
    const float* __restrict__ hidden,     // [M_ROWS, 48]
    const float* __restrict__ Ws)         // [1728, 48]
{
    __shared__ float Asm[HH][ASTRIDE];    // A^T : Asm[k][m]
    __shared__ float Bsm[HH][HH];         // Bsm[k][n] = Ws[bin*48+k][n]

    const int m0  = blockIdx.x * PM;
    const int bin = blockIdx.y;
    const int tid = threadIdx.x;

    // load A transposed: 128 rows x 48 k  (1536 float4)
    for (int l = tid; l < (PM * HH) / 4; l += 256) {
        int m  = l / (HH / 4);
        int kq = (l % (HH / 4)) * 4;
        float4 v = *(const float4*)&hidden[(m0 + m) * HH + kq];
        Asm[kq + 0][m] = v.x;
        Asm[kq + 1][m] = v.y;
        Asm[kq + 2][m] = v.z;
        Asm[kq + 3][m] = v.w;
    }
    // load B block: Ws rows [bin*48, bin*48+48)
    for (int l = tid; l < (HH * HH) / 4; l += 256) {
        int i = l / (HH / 4);
        int j = (l % (HH / 4)) * 4;
        *(float4*)&Bsm[i][j] = *(const float4*)&Ws[(bin * HH + i) * HH + j];
    }
    __syncthreads();

    const int ty = tid / 8;               // rows ty*4 .. ty*4+3   (32 groups)
    const int tx = tid % 8;               // col pairs at tx*6 + {0,2,4}

    u64 acc[4][3];
#pragma unroll
    for (int r = 0; r < 4; r++)
#pragma unroll
        for (int p = 0; p < 3; p++) acc[r][p] = pack2(0.0f, 0.0f);

#pragma unroll 12
    for (int k = 0; k < HH; k++) {
        float4 a = *(const float4*)&Asm[k][ty * 4];
        u64 b0 = *(const u64*)&Bsm[k][tx * 6 + 0];   // 8B aligned (24B offset)
        u64 b1 = *(const u64*)&Bsm[k][tx * 6 + 2];
        u64 b2 = *(const u64*)&Bsm[k][tx * 6 + 4];
        u64 ad[4] = { pack2(a.x, a.x), pack2(a.y, a.y),
                      pack2(a.z, a.z), pack2(a.w, a.w) };
#pragma unroll
        for (int r = 0; r < 4; r++) {
            acc[r][0] = fma2(ad[r], b0, acc[r][0]);
            acc[r][1] = fma2(ad[r], b1, acc[r][1]);
            acc[r][2] = fma2(ad[r], b2, acc[r][2]);
        }
    }

#pragma unroll
    for (int r = 0; r < 4; r++) {
        int row = m0 + ty * 4 + r;
        float2* dst = (float2*)&g_hw[row * K_SP + bin * HH + tx * 6];
        dst[0] = unpack2(acc[r][0]);
        dst[1] = unpack2(acc[r][1]);
        dst[2] = unpack2(acc[r][2]);
    }
}

// ---------------------------------------------------------------------------
// Kernel Q: per (a,c) row — bin episode agents, gather-sum hW rows,
// bias+relu, fused scene passthrough + velocity encoder.
// grid M_ROWS, block 192 = 8 b-groups x 24 threads (2 cols each).
// ---------------------------------------------------------------------------
__global__ void __launch_bounds__(192) gather_kernel(
    const float* __restrict__ position,   // [M_ROWS, 2]
    const int*   __restrict__ ntt,        // [nb]
    const float* __restrict__ scene,      // [M_ROWS, 64]
    const float* __restrict__ velocity,   // [M_ROWS, 2]
    const float* __restrict__ Wv,         // [2, 16]
    const float* __restrict__ bv,         // [16]
    const float* __restrict__ bs,         // [48]
    float* __restrict__ out,              // [M_ROWS, 128]
    int nb)
{
    const int row = blockIdx.x;           // a*NC + c
    const int a = row / NC;
    const int c = row % NC;
    const int tid = threadIdx.x;

    __shared__ int   s_bin[MAXE];
    __shared__ int   s_cnt[NB_BINS];
    __shared__ float s_inv[NB_BINS];
    __shared__ float s_red[8][HH];

    if (tid < NB_BINS) s_cnt[tid] = 0;

    // episode [start, end) containing agent a
    int start = 0, end = 0, cum = 0;
    for (int i = 0; i < nb; i++) {
        int s = ntt[i];
        if (a >= cum && a < cum + s) { start = cum; end = cum + s; }
        cum += s;
    }
    int esz = end - start;
    if (esz > MAXE) esz = MAXE;

    const float px = position[row * 2 + 0];
    const float py = position[row * 2 + 1];
    const float rlogf = 0.34657359027997264f;   // log(RMAX/RMIN)/NUM_RINGS
    const float PIf   = 3.14159265358979323846f;

    __syncthreads();

    // pass 1: bins + counts
    for (int b = tid; b < esz; b += 192) {
        int brow = (start + b) * NC + c;
        float xd = px - position[brow * 2 + 0];
        float yd = py - position[brow * 2 + 1];
        float dist = sqrtf(xd * xd + yd * yd);
        int ring = (int)floorf(logf(dist / 0.5f + 1e-6f) / rlogf);
        int bin = -1;
        if (ring >= 0 && ring < 6) {
            float theta = atan2f(yd, xd);
            int wedge = (int)floorf((theta + PIf - 1e-6f) / PIf / 2.0f * 6.0f);
            bin = ring * 6 + wedge;
            if (bin < 0 || bin >= NB_BINS) bin = -1;
        }
        s_bin[b] = bin;
        if (bin >= 0) atomicAdd(&s_cnt[bin], 1);
    }
    __syncthreads();
    if (tid < NB_BINS) s_inv[tid] = 1.0f / (float)max(s_cnt[tid], 1);
    __syncthreads();

    // pass 2: gather-sum over episode agents (2 cols/thread, 2 indep chains)
    const int bq = tid / 24;              // 0..7
    const int n0 = (tid % 24) * 2;        // even col -> 8B-aligned float2
    u64 acc0 = pack2(0.0f, 0.0f);
    u64 acc1 = pack2(0.0f, 0.0f);
    for (int b = bq; b < esz; b += 16) {
        int bin = s_bin[b];
        if (bin >= 0) {
            u64 v = *(const u64*)&g_hw[((start + b) * NC + c) * K_SP + bin * HH + n0];
            float inv = s_inv[bin];
            acc0 = fma2(v, pack2(inv, inv), acc0);
        }
        int b2 = b + 8;
        if (b2 < esz) {
            int bin2 = s_bin[b2];
            if (bin2 >= 0) {
                u64 v2 = *(const u64*)&g_hw[((start + b2) * NC + c) * K_SP + bin2 * HH + n0];
                float inv2 = s_inv[bin2];
                acc1 = fma2(v2, pack2(inv2, inv2), acc1);
            }
        }
    }
    float2 part = unpack2(fma2(pack2(1.0f, 1.0f), acc0, acc1));
    s_red[bq][n0]     = part.x;
    s_red[bq][n0 + 1] = part.y;

    // fused concat while the reduction lands: scene cols [0,64)
    for (int l = tid; l < CE; l += 192)
        out[row * OUT_C + l] = scene[row * CE + l];
    // velocity encoder cols [64,80)
    if (tid >= HH && tid < HH + VFC) {
        int o = tid - HH;
        float v = velocity[row * 2 + 0] * Wv[o]
                + velocity[row * 2 + 1] * Wv[VFC + o] + bv[o];
        out[row * OUT_C + CE + o] = fmaxf(v, 0.0f);
    }
    __syncthreads();

    // final reduce + bias + relu -> cols [80,128)
    if (tid < HH) {
        float t = ((s_red[0][tid] + s_red[1][tid]) + (s_red[2][tid] + s_red[3][tid]))
                + ((s_red[4][tid] + s_red[5][tid]) + (s_red[6][tid] + s_red[7][tid]));
        out[row * OUT_C + CE + VFC + tid] = fmaxf(t + bs[tid], 0.0f);
    }
}

// ---------------------------------------------------------------------------
extern "C" void kernel_launch(void* const* d_in, const int* in_sizes, int n_in,
                              void* d_out, int out_size)
{
    const float* hidden   = (const float*)d_in[0];
    const float* velocity = (const float*)d_in[1];
    const float* position = (const float*)d_in[2];
    const float* scene    = (const float*)d_in[3];
    const int*   ntt      = (const int*)d_in[4];
    const float* Wv       = (const float*)d_in[5];
    const float* bv       = (const float*)d_in[6];
    const float* Ws       = (const float*)d_in[7];
    const float* bs       = (const float*)d_in[8];
    float* out = (float*)d_out;
    int nb = in_sizes[4];

    hw_kernel<<<dim3(M_ROWS / PM, NB_BINS), 256>>>(hidden, Ws);
    gather_kernel<<<M_ROWS, 192>>>(position, ntt, scene, velocity,
                                   Wv, bv, bs, out, nb);
}